// round 8
// baseline (speedup 1.0000x reference)
#include <cuda_runtime.h>
#include <cuda_bf16.h>

#define Bb 8
#define Cc 128
#define HW 4096
#define HWP 1024
#define C8 16
#define C2 64

__device__ float phi_g  [Bb * C8 * HWP];  // [b][k][j]
__device__ float gsc_g  [Bb * C2 * HWP];  // [b][c2][j]

// ---------------- helpers ----------------
__device__ __forceinline__ unsigned long long pk2(float a, float b) {
    unsigned long long r; asm("mov.b64 %0, {%1, %2};" : "=l"(r) : "f"(a), "f"(b)); return r;
}
__device__ __forceinline__ unsigned long long fma2(unsigned long long a, unsigned long long b, unsigned long long c) {
    unsigned long long r; asm("fma.rn.f32x2 %0, %1, %2, %3;" : "=l"(r) : "l"(a), "l"(b), "l"(c)); return r;
}
__device__ __forceinline__ float2 upk2(unsigned long long a) {
    float2 r; asm("mov.b64 {%0, %1}, %2;" : "=f"(r.x), "=f"(r.y) : "l"(a)); return r;
}
__device__ __forceinline__ unsigned cvt2bf(float hi, float lo) {   // {upper=hi, lower=lo}
    unsigned r; asm("cvt.rn.bf16x2.f32 %0, %1, %2;" : "=r"(r) : "f"(hi), "f"(lo)); return r;
}
// hp = bf16x2(y|x) rounded; lp = residuals
__device__ __forceinline__ void hilo(float x, float y, unsigned &hp, unsigned &lp) {
    float xh = __bfloat162float(__float2bfloat16(x));
    float yh = __bfloat162float(__float2bfloat16(y));
    hp = cvt2bf(y, x);
    lp = cvt2bf(y - yh, x - xh);
}
__device__ __forceinline__ void mma16816(float* d, const unsigned* a, const unsigned* b) {
    asm volatile("mma.sync.aligned.m16n8k16.row.col.f32.bf16.bf16.f32 "
        "{%0,%1,%2,%3}, {%4,%5,%6,%7}, {%8,%9}, {%0,%1,%2,%3};"
        : "+f"(d[0]), "+f"(d[1]), "+f"(d[2]), "+f"(d[3])
        : "r"(a[0]), "r"(a[1]), "r"(a[2]), "r"(a[3]), "r"(b[0]), "r"(b[1]));
}

// ---------------- Kernel 1: phi/g projection fused with 2x2 maxpool ----------------
__global__ void __launch_bounds__(256) projpool_kernel(
    const float* __restrict__ x, const float* __restrict__ w_phi, const float* __restrict__ w_g)
{
    __shared__ __align__(16) unsigned long long w2s[C8 * Cc];
    int gy = blockIdx.y;
    const float* w = (gy == 0) ? w_phi : (w_g + (size_t)(gy - 1) * C8 * Cc);
    for (int idx = threadIdx.x; idx < C8 * Cc; idx += 256) { float f = w[idx]; w2s[idx] = pk2(f, f); }
    __syncthreads();

    int t = blockIdx.x * 256 + threadIdx.x;   // 0..8191
    int b = t >> 10, j = t & (HWP - 1);
    int py = j >> 5, px = j & 31;
    const float* xb = x + ((size_t)b << 19) + py * 128 + px * 2;

    unsigned long long a01[C8], a23[C8];
#pragma unroll
    for (int k = 0; k < C8; k++) { a01[k] = 0ULL; a23[k] = 0ULL; }
#pragma unroll 2
    for (int c = 0; c < Cc; c++) {
        const float* p = xb + ((size_t)c << 12);
        unsigned long long x01 = *(const unsigned long long*)p;
        unsigned long long x23 = *(const unsigned long long*)(p + 64);
#pragma unroll
        for (int k = 0; k < C8; k++) {
            unsigned long long w2 = w2s[k * Cc + c];
            a01[k] = fma2(w2, x01, a01[k]);
            a23[k] = fma2(w2, x23, a23[k]);
        }
    }
#pragma unroll
    for (int k = 0; k < C8; k++) {
        float2 v01 = upk2(a01[k]), v23 = upk2(a23[k]);
        float m = fmaxf(fmaxf(v01.x, v01.y), fmaxf(v23.x, v23.y));
        if (gy == 0) phi_g[(((size_t)b * C8 + k) << 10) + j] = m;
        else         gsc_g[(((size_t)b * C2 + (gy - 1) * C8 + k) << 10) + j] = m;
    }
}

// ---------------- Kernel 2: mma.sync flash attention (theta fused) + w_o conv + residual ----------------
// grid (32, 8), 256 threads. Prologue: theta = w_theta @ x via MMA (D-frag -> A-frag chaining).
// Main: 8 chunks of 128 j, double-buffered smem, per-kk S->exp->O pipeline.
// smem (dynamic 78336B):
//   prologue: XT_HI[128q][272B] @0, XT_LO @34816, WT_HI[16][272B] @69632, WT_LO @73984
//   loop:     buf{0,1} @ {0, 27648}: PHI_HI[128j][36B] +0, PHI_LO +4608, G[64c2][272B] +9216
//   epilogue: W_HI[128co][136B] @0, W_LO @17408
#define XT_HI 0
#define XT_LO 34816
#define WT_HI 69632
#define WT_LO 73984
#define BUFSTRIDE 27648
#define PHI_HI 0
#define PHI_LO 4608
#define G_OFF  9216
#define W_HI   0
#define W_LO   17408
#define SMEM_SZ 78336

__global__ void __launch_bounds__(256, 2) attn_kernel(
    const float* __restrict__ x, const float* __restrict__ w_theta,
    const float* __restrict__ w_o, const float* __restrict__ gamma_p,
    float* __restrict__ out)
{
    extern __shared__ __align__(16) char smem[];
    const int tid = threadIdx.x;
    const int w = tid >> 5, lane = tid & 31;
    const int gr = lane >> 2, tig = lane & 3;
    const int b = blockIdx.y;
    const int q0 = blockIdx.x * 128 + w * 16 + gr;   // this thread's first query row
    const int wq = w * 16;                            // warp's q base within block

    // ================= prologue: theta via MMA =================
    {
        const float* xb = x + ((size_t)b << 19) + blockIdx.x * 128;
#pragma unroll 8
        for (int u = 0; u < 32; u++) {
            int cp = u * 2 + (tid >> 7);   // c-pair 0..63
            int q  = tid & 127;
            int c0 = cp * 2;
            float v0 = xb[((size_t)c0 << 12) + q];
            float v1 = xb[((size_t)(c0 + 1) << 12) + q];
            unsigned hp, lp; hilo(v0, v1, hp, lp);
            *(unsigned*)(smem + XT_HI + q * 272 + c0 * 2) = hp;
            *(unsigned*)(smem + XT_LO + q * 272 + c0 * 2) = lp;
        }
#pragma unroll
        for (int idx = tid; idx < 1024; idx += 256) {
            int n = idx >> 6, cp = idx & 63;
            float v0 = w_theta[n * 128 + cp * 2], v1 = w_theta[n * 128 + cp * 2 + 1];
            unsigned hp, lp; hilo(v0, v1, hp, lp);
            *(unsigned*)(smem + WT_HI + n * 272 + cp * 4) = hp;
            *(unsigned*)(smem + WT_LO + n * 272 + cp * 4) = lp;
        }
    }
    __syncthreads();

    unsigned ahi[4], alo[4];
    {
        float th_d[2][4];
#pragma unroll
        for (int nt = 0; nt < 2; nt++)
#pragma unroll
            for (int r = 0; r < 4; r++) th_d[nt][r] = 0.0f;
#pragma unroll
        for (int kc = 0; kc < 8; kc++) {
            const char* xrh = smem + XT_HI + (wq + gr) * 272 + kc * 32 + tig * 4;
            const char* xrl = smem + XT_LO + (wq + gr) * 272 + kc * 32 + tig * 4;
            unsigned xh[4], xl[4];
            xh[0] = *(const unsigned*)xrh;                xh[2] = *(const unsigned*)(xrh + 16);
            xh[1] = *(const unsigned*)(xrh + 8 * 272);    xh[3] = *(const unsigned*)(xrh + 8 * 272 + 16);
            xl[0] = *(const unsigned*)xrl;                xl[2] = *(const unsigned*)(xrl + 16);
            xl[1] = *(const unsigned*)(xrl + 8 * 272);    xl[3] = *(const unsigned*)(xrl + 8 * 272 + 16);
#pragma unroll
            for (int nt = 0; nt < 2; nt++) {
                const char* wrh = smem + WT_HI + (nt * 8 + gr) * 272 + kc * 32 + tig * 4;
                const char* wrl = smem + WT_LO + (nt * 8 + gr) * 272 + kc * 32 + tig * 4;
                unsigned bh[2] = { *(const unsigned*)wrh, *(const unsigned*)(wrh + 16) };
                unsigned bl[2] = { *(const unsigned*)wrl, *(const unsigned*)(wrl + 16) };
                mma16816(th_d[nt], xh, bh);
                mma16816(th_d[nt], xh, bl);
                mma16816(th_d[nt], xl, bh);
            }
        }
        hilo(th_d[0][0], th_d[0][1], ahi[0], alo[0]);
        hilo(th_d[0][2], th_d[0][3], ahi[1], alo[1]);
        hilo(th_d[1][0], th_d[1][1], ahi[2], alo[2]);
        hilo(th_d[1][2], th_d[1][3], ahi[3], alo[3]);
    }
    __syncthreads();

    // ================= main loop =================
    float oacc[8][4];
#pragma unroll
    for (int nt = 0; nt < 8; nt++)
#pragma unroll
        for (int r = 0; r < 4; r++) oacc[nt][r] = 0.0f;
    float es0 = 0.0f, es1 = 0.0f;

    for (int ch = 0; ch < 8; ch++) {
        const int j0 = ch << 7;
        char* buf = smem + (ch & 1) * BUFSTRIDE;
        // ---- stage phi chunk -> [j][k] bf16 hi/lo ----
        {
            int jj = tid & 127, ks = (tid >> 7) << 3;
            const float* src = phi_g + (((size_t)(b * 16 + ks)) << 10) + j0 + jj;
            char* hb = buf + PHI_HI + jj * 36 + ks * 2;
            char* lb = buf + PHI_LO + jj * 36 + ks * 2;
#pragma unroll
            for (int u = 0; u < 8; u++) {
                float v = src[(size_t)u << 10];
                float vh = __bfloat162float(__float2bfloat16(v));
                *(__nv_bfloat16*)(hb + 2 * u) = __float2bfloat16(v);
                *(__nv_bfloat16*)(lb + 2 * u) = __float2bfloat16(v - vh);
            }
        }
        // ---- stage g chunk -> [c2][j] bf16 (hi only), row stride 272B ----
        {
            int c2 = tid >> 2, jq = (tid & 3) << 5;
            const float4* src = (const float4*)(gsc_g + (((size_t)(b * 64 + c2)) << 10) + j0 + jq);
            char* dst = buf + G_OFF + c2 * 272 + jq * 2;
#pragma unroll
            for (int u = 0; u < 8; u++) {
                float4 v = src[u];
                unsigned p0 = cvt2bf(v.y, v.x), p1 = cvt2bf(v.w, v.z);
                *(unsigned long long*)(dst + 8 * u) = ((unsigned long long)p1 << 32) | p0;
            }
        }
        __syncthreads();

        // ---- per-kk: 2 S tiles -> exp -> 8 O MMAs ----
#pragma unroll
        for (int kk = 0; kk < 8; kk++) {
            float e_t0[4], e_t1[4];
            {   // tile t0 = 2kk : j = 16kk + 0..7
                int jl = (kk << 4) + gr;
                const char* ph = buf + PHI_HI + jl * 36 + tig * 4;
                const char* pl = buf + PHI_LO + jl * 36 + tig * 4;
                unsigned bh[2] = { *(const unsigned*)ph, *(const unsigned*)(ph + 16) };
                unsigned bl[2] = { *(const unsigned*)pl, *(const unsigned*)(pl + 16) };
                float d[4] = {0.f, 0.f, 0.f, 0.f};
                mma16816(d, ahi, bh);
                mma16816(d, ahi, bl);
                mma16816(d, alo, bh);
                e_t0[0] = __expf(d[0]); e_t0[1] = __expf(d[1]);
                e_t0[2] = __expf(d[2]); e_t0[3] = __expf(d[3]);
            }
            {   // tile t1 = 2kk+1 : j = 16kk + 8..15
                int jl = (kk << 4) + 8 + gr;
                const char* ph = buf + PHI_HI + jl * 36 + tig * 4;
                const char* pl = buf + PHI_LO + jl * 36 + tig * 4;
                unsigned bh[2] = { *(const unsigned*)ph, *(const unsigned*)(ph + 16) };
                unsigned bl[2] = { *(const unsigned*)pl, *(const unsigned*)(pl + 16) };
                float d[4] = {0.f, 0.f, 0.f, 0.f};
                mma16816(d, ahi, bh);
                mma16816(d, ahi, bl);
                mma16816(d, alo, bh);
                e_t1[0] = __expf(d[0]); e_t1[1] = __expf(d[1]);
                e_t1[2] = __expf(d[2]); e_t1[3] = __expf(d[3]);
            }
            es0 += (e_t0[0] + e_t0[1]) + (e_t1[0] + e_t1[1]);
            es1 += (e_t0[2] + e_t0[3]) + (e_t1[2] + e_t1[3]);
            unsigned a[4];
            a[0] = cvt2bf(e_t0[1], e_t0[0]);
            a[1] = cvt2bf(e_t0[3], e_t0[2]);
            a[2] = cvt2bf(e_t1[1], e_t1[0]);
            a[3] = cvt2bf(e_t1[3], e_t1[2]);
#pragma unroll
            for (int nt = 0; nt < 8; nt++) {
                int c2 = (nt << 3) + gr;
                const char* gp = buf + G_OFF + c2 * 272 + kk * 32 + tig * 4;
                unsigned bb[2] = { *(const unsigned*)gp, *(const unsigned*)(gp + 16) };
                mma16816(oacc[nt], a, bb);
            }
        }
    }
    __syncthreads();

    // ---- softmax normalization ----
    es0 += __shfl_xor_sync(0xFFFFFFFFu, es0, 1);
    es0 += __shfl_xor_sync(0xFFFFFFFFu, es0, 2);
    es1 += __shfl_xor_sync(0xFFFFFFFFu, es1, 1);
    es1 += __shfl_xor_sync(0xFFFFFFFFu, es1, 2);
    float i0 = 1.0f / es0, i1 = 1.0f / es1;
#pragma unroll
    for (int nt = 0; nt < 8; nt++) {
        oacc[nt][0] *= i0; oacc[nt][1] *= i0;
        oacc[nt][2] *= i1; oacc[nt][3] *= i1;
    }

    // ---- stage w_o -> [co][c2] bf16 hi/lo, row stride 136B ----
    {
        int co = tid >> 1, c2h = (tid & 1) << 5;
        const float4* src = (const float4*)(w_o + co * 64 + c2h);
        char* dh = smem + W_HI + co * 136 + c2h * 2;
        char* dl = smem + W_LO + co * 136 + c2h * 2;
#pragma unroll
        for (int u = 0; u < 8; u++) {
            float4 v = src[u];
            float hx = __bfloat162float(__float2bfloat16(v.x));
            float hy = __bfloat162float(__float2bfloat16(v.y));
            float hz = __bfloat162float(__float2bfloat16(v.z));
            float hw = __bfloat162float(__float2bfloat16(v.w));
            unsigned h0 = cvt2bf(v.y, v.x), h1 = cvt2bf(v.w, v.z);
            unsigned l0 = cvt2bf(v.y - hy, v.x - hx), l1 = cvt2bf(v.w - hw, v.z - hz);
            *(unsigned long long*)(dh + 8 * u) = ((unsigned long long)h1 << 32) | h0;
            *(unsigned long long*)(dl + 8 * u) = ((unsigned long long)l1 << 32) | l0;
        }
    }
    __syncthreads();

    // ---- out = gamma * (o @ w_o^T) + x ----
    const float gamma = *gamma_p;
    const float* xb = x   + ((size_t)b << 19);
    float*       ob = out + ((size_t)b << 19);

    unsigned oa[4][4];
#pragma unroll
    for (int kk = 0; kk < 4; kk++) {
        oa[kk][0] = cvt2bf(oacc[2*kk][1],   oacc[2*kk][0]);
        oa[kk][1] = cvt2bf(oacc[2*kk][3],   oacc[2*kk][2]);
        oa[kk][2] = cvt2bf(oacc[2*kk+1][1], oacc[2*kk+1][0]);
        oa[kk][3] = cvt2bf(oacc[2*kk+1][3], oacc[2*kk+1][2]);
    }

#pragma unroll
    for (int h = 0; h < 2; h++) {
        float dd[8][4];
#pragma unroll
        for (int nt = 0; nt < 8; nt++)
#pragma unroll
            for (int r = 0; r < 4; r++) dd[nt][r] = 0.0f;
#pragma unroll
        for (int kk = 0; kk < 4; kk++) {
#pragma unroll
            for (int nt = 0; nt < 8; nt++) {
                int co = ((h << 3) + nt) * 8 + gr;
                const char* wh = smem + W_HI + co * 136 + kk * 32 + tig * 4;
                const char* wl = smem + W_LO + co * 136 + kk * 32 + tig * 4;
                unsigned b0[2] = { *(const unsigned*)wh, *(const unsigned*)(wh + 16) };
                unsigned b1[2] = { *(const unsigned*)wl, *(const unsigned*)(wl + 16) };
                mma16816(dd[nt], oa[kk], b0);
                mma16816(dd[nt], oa[kk], b1);
            }
        }
#pragma unroll
        for (int nt = 0; nt < 8; nt++) {
            int co0 = (((h << 3) + nt) * 8 + tig * 2);
            size_t i00 = ((size_t)co0 << 12) + q0;
            size_t i01 = ((size_t)(co0 + 1) << 12) + q0;
            ob[i00]     = fmaf(gamma, dd[nt][0], xb[i00]);
            ob[i01]     = fmaf(gamma, dd[nt][1], xb[i01]);
            ob[i00 + 8] = fmaf(gamma, dd[nt][2], xb[i00 + 8]);
            ob[i01 + 8] = fmaf(gamma, dd[nt][3], xb[i01 + 8]);
        }
    }
}

extern "C" void kernel_launch(void* const* d_in, const int* in_sizes, int n_in,
                              void* d_out, int out_size)
{
    const float* x       = (const float*)d_in[0];
    const float* w_theta = (const float*)d_in[1];
    const float* w_phi   = (const float*)d_in[2];
    const float* w_g     = (const float*)d_in[3];
    const float* w_o     = (const float*)d_in[4];
    const float* gamma_p = (const float*)d_in[5];
    float* out = (float*)d_out;

    cudaFuncSetAttribute(attn_kernel, cudaFuncAttributeMaxDynamicSharedMemorySize, SMEM_SZ);

    projpool_kernel<<<dim3(32, 5), 256>>>(x, w_phi, w_g);
    attn_kernel<<<dim3(32, 8), 256, SMEM_SZ>>>(x, w_theta, w_o, gamma_p, out);
}

// round 11
// speedup vs baseline: 1.5005x; 1.5005x over previous
#include <cuda_runtime.h>
#include <cuda_bf16.h>

#define Bb 8
#define Cc 128
#define HW 4096
#define HWP 1024
#define C8 16
#define C2 64

__device__ float theta_g[Bb * C8 * HW];   // [b][k][i]
__device__ float phi_g  [Bb * C8 * HWP];  // [b][k][j]
__device__ float gsc_g  [Bb * C2 * HWP];  // [b][c2][j]

// ---------------- helpers ----------------
__device__ __forceinline__ unsigned long long pk2(float a, float b) {
    unsigned long long r; asm("mov.b64 %0, {%1, %2};" : "=l"(r) : "f"(a), "f"(b)); return r;
}
__device__ __forceinline__ unsigned long long fma2(unsigned long long a, unsigned long long b, unsigned long long c) {
    unsigned long long r; asm("fma.rn.f32x2 %0, %1, %2, %3;" : "=l"(r) : "l"(a), "l"(b), "l"(c)); return r;
}
__device__ __forceinline__ float2 upk2(unsigned long long a) {
    float2 r; asm("mov.b64 {%0, %1}, %2;" : "=f"(r.x), "=f"(r.y) : "l"(a)); return r;
}
__device__ __forceinline__ unsigned cvt2bf(float hi, float lo) {   // {upper=hi, lower=lo}
    unsigned r; asm("cvt.rn.bf16x2.f32 %0, %1, %2;" : "=r"(r) : "f"(hi), "f"(lo)); return r;
}
__device__ __forceinline__ void hilo(float x, float y, unsigned &hp, unsigned &lp) {
    float xh = __bfloat162float(__float2bfloat16(x));
    float yh = __bfloat162float(__float2bfloat16(y));
    hp = cvt2bf(y, x);
    lp = cvt2bf(y - yh, x - xh);
}
__device__ __forceinline__ void mma16816(float* d, const unsigned* a, const unsigned* b) {
    asm volatile("mma.sync.aligned.m16n8k16.row.col.f32.bf16.bf16.f32 "
        "{%0,%1,%2,%3}, {%4,%5,%6,%7}, {%8,%9}, {%0,%1,%2,%3};"
        : "+f"(d[0]), "+f"(d[1]), "+f"(d[2]), "+f"(d[3])
        : "r"(a[0]), "r"(a[1]), "r"(a[2]), "r"(a[3]), "r"(b[0]), "r"(b[1]));
}
__device__ __forceinline__ void ldsm4(unsigned addr, unsigned &r0, unsigned &r1, unsigned &r2, unsigned &r3) {
    asm volatile("ldmatrix.sync.aligned.m8n8.x4.shared.b16 {%0,%1,%2,%3}, [%4];"
        : "=r"(r0), "=r"(r1), "=r"(r2), "=r"(r3) : "r"(addr));
}
__device__ __forceinline__ unsigned smem_u32(const void* p) {
    unsigned a; asm("{ .reg .u64 t; cvta.to.shared.u64 t, %1; cvt.u32.u64 %0, t; }" : "=r"(a) : "l"(p)); return a;
}

// ---------------- Kernel 1: theta projection ----------------
__global__ void __launch_bounds__(128) theta_kernel(
    const float* __restrict__ x, const float* __restrict__ w_theta)
{
    __shared__ __align__(16) float ws[C8 * Cc];
    for (int idx = threadIdx.x; idx < C8 * Cc; idx += 128) ws[idx] = w_theta[idx];
    __syncthreads();
    int t = blockIdx.x * 128 + threadIdx.x;
    int b = t >> 12, pix = t & (HW - 1);
    const float* xb = x + ((size_t)b << 19) + pix;
    unsigned long long acc[C8];
#pragma unroll
    for (int k = 0; k < C8; k++) acc[k] = 0ULL;
#pragma unroll 8
    for (int c = 0; c < Cc; c += 2) {
        unsigned long long x2 = pk2(xb[(size_t)c << 12], xb[(size_t)(c + 1) << 12]);
#pragma unroll
        for (int k = 0; k < C8; k++)
            acc[k] = fma2(*(const unsigned long long*)&ws[k * Cc + c], x2, acc[k]);
    }
#pragma unroll
    for (int k = 0; k < C8; k++) {
        float2 v = upk2(acc[k]);
        theta_g[(((size_t)b * C8 + k) << 12) + pix] = v.x + v.y;
    }
}

// ---------------- Kernel 2: phi/g projection fused with 2x2 maxpool ----------------
__global__ void __launch_bounds__(256) projpool_kernel(
    const float* __restrict__ x, const float* __restrict__ w_phi, const float* __restrict__ w_g)
{
    __shared__ __align__(16) unsigned long long w2s[C8 * Cc];
    int gy = blockIdx.y;
    const float* w = (gy == 0) ? w_phi : (w_g + (size_t)(gy - 1) * C8 * Cc);
    for (int idx = threadIdx.x; idx < C8 * Cc; idx += 256) { float f = w[idx]; w2s[idx] = pk2(f, f); }
    __syncthreads();

    int t = blockIdx.x * 256 + threadIdx.x;   // 0..8191
    int b = t >> 10, j = t & (HWP - 1);
    int py = j >> 5, px = j & 31;
    const float* xb = x + ((size_t)b << 19) + py * 128 + px * 2;

    unsigned long long a01[C8], a23[C8];
#pragma unroll
    for (int k = 0; k < C8; k++) { a01[k] = 0ULL; a23[k] = 0ULL; }
#pragma unroll 2
    for (int c = 0; c < Cc; c++) {
        const float* p = xb + ((size_t)c << 12);
        unsigned long long x01 = *(const unsigned long long*)p;
        unsigned long long x23 = *(const unsigned long long*)(p + 64);
#pragma unroll
        for (int k = 0; k < C8; k++) {
            unsigned long long w2 = w2s[k * Cc + c];
            a01[k] = fma2(w2, x01, a01[k]);
            a23[k] = fma2(w2, x23, a23[k]);
        }
    }
#pragma unroll
    for (int k = 0; k < C8; k++) {
        float2 v01 = upk2(a01[k]), v23 = upk2(a23[k]);
        float m = fmaxf(fmaxf(v01.x, v01.y), fmaxf(v23.x, v23.y));
        if (gy == 0) phi_g[(((size_t)b * C8 + k) << 10) + j] = m;
        else         gsc_g[(((size_t)b * C2 + (gy - 1) * C8 + k) << 10) + j] = m;
    }
}

// ---------------- Kernel 3: mma.sync flash attention + w_o conv + residual ----------------
// grid (32, 8), 256 threads. 8 chunks of 128 j. B-frags via ldmatrix (16B-aligned strides).
// smem: PHI_HI [128j][48B] @0, PHI_LO @6144, G [64c2][272B] @12288 (29696 total);
// epilogue reuse: W_HI [128co][144B] @0, W_LO @18432 (36864 total).
#define PHI_HI 0
#define PHI_LO 6144
#define G_OFF  12288
#define W_HI   0
#define W_LO   18432
#define SMEM_SZ 36864

__global__ void __launch_bounds__(256, 2) attn_kernel(
    const float* __restrict__ x, const float* __restrict__ w_o,
    const float* __restrict__ gamma_p, float* __restrict__ out)
{
    __shared__ __align__(16) char smem[SMEM_SZ];
    const int tid = threadIdx.x;
    const int w = tid >> 5, lane = tid & 31;
    const int gr = lane >> 2, tig = lane & 3;
    const int b = blockIdx.y;
    const int q0 = blockIdx.x * 128 + w * 16 + gr;
    const unsigned sbase = smem_u32(smem);

    // ldmatrix lane-address decomposition: matrix idx = lane/8 -> {col-16B, row-block}
    const int lrow = lane & 7;
    const int lcolsel = (lane >> 3) & 1;   // 0: k/j 0..7, 1: 8..15
    const int lblk = lane >> 4;            // 0: rows +0..7, 1: rows +8..15
    const unsigned phiH = sbase + PHI_HI + (unsigned)((lblk * 8 + lrow) * 48 + lcolsel * 16);
    const unsigned phiL = sbase + PHI_LO + (unsigned)((lblk * 8 + lrow) * 48 + lcolsel * 16);
    const unsigned gB   = sbase + G_OFF  + (unsigned)((lblk * 8 + lrow) * 272 + lcolsel * 16);
    const unsigned wB   = sbase + W_HI   + (unsigned)((lblk * 8 + lrow) * 144 + lcolsel * 16);

    // ---- theta A fragments (hi/lo), K=16 ----
    unsigned ahi[4], alo[4];
    {
        const float* tb = theta_g + ((size_t)b << 16);
        int k0 = tig * 2;
        float x00 = tb[((size_t)k0 << 12) + q0],       x01 = tb[((size_t)(k0+1) << 12) + q0];
        float x10 = tb[((size_t)k0 << 12) + q0+8],     x11 = tb[((size_t)(k0+1) << 12) + q0+8];
        float x20 = tb[((size_t)(k0+8) << 12) + q0],   x21 = tb[((size_t)(k0+9) << 12) + q0];
        float x30 = tb[((size_t)(k0+8) << 12) + q0+8], x31 = tb[((size_t)(k0+9) << 12) + q0+8];
        hilo(x00, x01, ahi[0], alo[0]);
        hilo(x10, x11, ahi[1], alo[1]);
        hilo(x20, x21, ahi[2], alo[2]);
        hilo(x30, x31, ahi[3], alo[3]);
    }

    float oacc[8][4];
#pragma unroll
    for (int nt = 0; nt < 8; nt++)
#pragma unroll
        for (int r = 0; r < 4; r++) oacc[nt][r] = 0.0f;
    float es0 = 0.0f, es1 = 0.0f;

    for (int ch = 0; ch < 8; ch++) {
        const int j0 = ch << 7;
        // ---- stage phi chunk -> [j][k] bf16 hi/lo, row stride 48B ----
        {
            int jj = tid & 127, ks = (tid >> 7) << 3;
            const float* src = phi_g + (((size_t)(b * 16 + ks)) << 10) + j0 + jj;
            char* hb = smem + PHI_HI + jj * 48 + ks * 2;
            char* lb = smem + PHI_LO + jj * 48 + ks * 2;
#pragma unroll
            for (int u = 0; u < 8; u++) {
                float v = src[(size_t)u << 10];
                float vh = __bfloat162float(__float2bfloat16(v));
                *(__nv_bfloat16*)(hb + 2 * u) = __float2bfloat16(v);
                *(__nv_bfloat16*)(lb + 2 * u) = __float2bfloat16(v - vh);
            }
        }
        // ---- stage g chunk -> [c2][j] bf16 (hi only), row stride 272B ----
        {
            int c2 = tid >> 2, jq = (tid & 3) << 5;
            const float4* src = (const float4*)(gsc_g + (((size_t)(b * 64 + c2)) << 10) + j0 + jq);
            char* dst = smem + G_OFF + c2 * 272 + jq * 2;
#pragma unroll
            for (int u = 0; u < 8; u++) {
                float4 v = src[u];
                unsigned p0 = cvt2bf(v.y, v.x), p1 = cvt2bf(v.w, v.z);
                *(unsigned long long*)(dst + 8 * u) = ((unsigned long long)p1 << 32) | p0;
            }
        }
        __syncthreads();

        // ---- S phase: 8 tile-pairs via ldmatrix, exp, pack P ----
        unsigned pp[16][2];
#pragma unroll
        for (int tp = 0; tp < 8; tp++) {
            unsigned h0, h1, h2, h3, l0, l1, l2, l3;
            ldsm4(phiH + tp * 768u, h0, h1, h2, h3);
            ldsm4(phiL + tp * 768u, l0, l1, l2, l3);
            {
                unsigned bh[2] = { h0, h1 }, bl[2] = { l0, l1 };
                float d[4] = {0.f, 0.f, 0.f, 0.f};
                mma16816(d, ahi, bh);
                mma16816(d, ahi, bl);
                mma16816(d, alo, bh);
                float e0 = __expf(d[0]), e1 = __expf(d[1]), e2 = __expf(d[2]), e3 = __expf(d[3]);
                es0 += e0 + e1; es1 += e2 + e3;
                pp[2*tp][0] = cvt2bf(e1, e0);
                pp[2*tp][1] = cvt2bf(e3, e2);
            }
            {
                unsigned bh[2] = { h2, h3 }, bl[2] = { l2, l3 };
                float d[4] = {0.f, 0.f, 0.f, 0.f};
                mma16816(d, ahi, bh);
                mma16816(d, ahi, bl);
                mma16816(d, alo, bh);
                float e0 = __expf(d[0]), e1 = __expf(d[1]), e2 = __expf(d[2]), e3 = __expf(d[3]);
                es0 += e0 + e1; es1 += e2 + e3;
                pp[2*tp+1][0] = cvt2bf(e1, e0);
                pp[2*tp+1][1] = cvt2bf(e3, e2);
            }
        }
        // ---- O phase: O += P @ g^T, g frags via ldmatrix ----
#pragma unroll
        for (int kk = 0; kk < 8; kk++) {
            unsigned a[4] = { pp[2*kk][0], pp[2*kk][1], pp[2*kk+1][0], pp[2*kk+1][1] };
#pragma unroll
            for (int u = 0; u < 4; u++) {
                unsigned g0, g1, g2, g3;
                ldsm4(gB + (unsigned)(u * 16 * 272 + kk * 32), g0, g1, g2, g3);
                unsigned b0[2] = { g0, g1 }, b1[2] = { g2, g3 };
                mma16816(oacc[2*u],     a, b0);
                mma16816(oacc[2*u + 1], a, b1);
            }
        }
        __syncthreads();
    }

    // ---- softmax normalization ----
    es0 += __shfl_xor_sync(0xFFFFFFFFu, es0, 1);
    es0 += __shfl_xor_sync(0xFFFFFFFFu, es0, 2);
    es1 += __shfl_xor_sync(0xFFFFFFFFu, es1, 1);
    es1 += __shfl_xor_sync(0xFFFFFFFFu, es1, 2);
    float i0 = 1.0f / es0, i1 = 1.0f / es1;
#pragma unroll
    for (int nt = 0; nt < 8; nt++) {
        oacc[nt][0] *= i0; oacc[nt][1] *= i0;
        oacc[nt][2] *= i1; oacc[nt][3] *= i1;
    }

    // ---- stage w_o -> [co][c2] bf16 hi/lo, row stride 144B ----
    {
        int co = tid >> 1, c2h = (tid & 1) << 5;
        const float4* src = (const float4*)(w_o + co * 64 + c2h);
        char* dh = smem + W_HI + co * 144 + c2h * 2;
        char* dl = smem + W_LO + co * 144 + c2h * 2;
#pragma unroll
        for (int u = 0; u < 8; u++) {
            float4 v = src[u];
            float hx = __bfloat162float(__float2bfloat16(v.x));
            float hy = __bfloat162float(__float2bfloat16(v.y));
            float hz = __bfloat162float(__float2bfloat16(v.z));
            float hw = __bfloat162float(__float2bfloat16(v.w));
            unsigned h0 = cvt2bf(v.y, v.x), h1 = cvt2bf(v.w, v.z);
            unsigned l0 = cvt2bf(v.y - hy, v.x - hx), l1 = cvt2bf(v.w - hw, v.z - hz);
            *(unsigned long long*)(dh + 8 * u) = ((unsigned long long)h1 << 32) | h0;
            *(unsigned long long*)(dl + 8 * u) = ((unsigned long long)l1 << 32) | l0;
        }
    }
    __syncthreads();

    // ---- out = gamma * (o @ w_o^T) + x ----
    const float gamma = *gamma_p;
    const float* xb = x   + ((size_t)b << 19);
    float*       ob = out + ((size_t)b << 19);

    unsigned oa[4][4];
#pragma unroll
    for (int kk = 0; kk < 4; kk++) {
        oa[kk][0] = cvt2bf(oacc[2*kk][1],   oacc[2*kk][0]);
        oa[kk][1] = cvt2bf(oacc[2*kk][3],   oacc[2*kk][2]);
        oa[kk][2] = cvt2bf(oacc[2*kk+1][1], oacc[2*kk+1][0]);
        oa[kk][3] = cvt2bf(oacc[2*kk+1][3], oacc[2*kk+1][2]);
    }

#pragma unroll
    for (int h = 0; h < 2; h++) {
        float dd[8][4];
#pragma unroll
        for (int nt = 0; nt < 8; nt++)
#pragma unroll
            for (int r = 0; r < 4; r++) dd[nt][r] = 0.0f;
#pragma unroll
        for (int kk = 0; kk < 4; kk++) {
#pragma unroll
            for (int u = 0; u < 4; u++) {   // co-blocks {h*64 + u*16 .. +15}
                unsigned wh0, wh1, wh2, wh3, wl0, wl1, wl2, wl3;
                unsigned off = (unsigned)((h * 64 + u * 16) * 144 + kk * 32);
                ldsm4(wB + off,                     wh0, wh1, wh2, wh3);
                ldsm4(wB + off + (unsigned)W_LO,   wl0, wl1, wl2, wl3);
                unsigned b0[2] = { wh0, wh1 }, b1[2] = { wl0, wl1 };
                unsigned b2[2] = { wh2, wh3 }, b3[2] = { wl2, wl3 };
                mma16816(dd[2*u],     oa[kk], b0);
                mma16816(dd[2*u],     oa[kk], b1);
                mma16816(dd[2*u + 1], oa[kk], b2);
                mma16816(dd[2*u + 1], oa[kk], b3);
            }
        }
#pragma unroll
        for (int nt = 0; nt < 8; nt++) {
            int co0 = (((h << 3) + nt) * 8 + tig * 2);
            size_t i00 = ((size_t)co0 << 12) + q0;
            size_t i01 = ((size_t)(co0 + 1) << 12) + q0;
            ob[i00]     = fmaf(gamma, dd[nt][0], xb[i00]);
            ob[i01]     = fmaf(gamma, dd[nt][1], xb[i01]);
            ob[i00 + 8] = fmaf(gamma, dd[nt][2], xb[i00 + 8]);
            ob[i01 + 8] = fmaf(gamma, dd[nt][3], xb[i01 + 8]);
        }
    }
}

extern "C" void kernel_launch(void* const* d_in, const int* in_sizes, int n_in,
                              void* d_out, int out_size)
{
    const float* x       = (const float*)d_in[0];
    const float* w_theta = (const float*)d_in[1];
    const float* w_phi   = (const float*)d_in[2];
    const float* w_g     = (const float*)d_in[3];
    const float* w_o     = (const float*)d_in[4];
    const float* gamma_p = (const float*)d_in[5];
    float* out = (float*)d_out;

    theta_kernel<<<256, 128>>>(x, w_theta);
    projpool_kernel<<<dim3(32, 5), 256>>>(x, w_phi, w_g);
    attn_kernel<<<dim3(32, 8), 256>>>(x, w_o, gamma_p, out);
}

// round 16
// speedup vs baseline: 1.6322x; 1.0878x over previous
#include <cuda_runtime.h>
#include <cuda_bf16.h>

#define Bb 8
#define Cc 128
#define HW 4096
#define HWP 1024
#define C8 16
#define C2 64

__device__ float phi_g  [Bb * C8 * HWP];  // [b][k][j]
__device__ float gsc_g  [Bb * C2 * HWP];  // [b][c2][j]

// ---------------- helpers ----------------
__device__ __forceinline__ unsigned long long pk2(float a, float b) {
    unsigned long long r; asm("mov.b64 %0, {%1, %2};" : "=l"(r) : "f"(a), "f"(b)); return r;
}
__device__ __forceinline__ unsigned long long fma2(unsigned long long a, unsigned long long b, unsigned long long c) {
    unsigned long long r; asm("fma.rn.f32x2 %0, %1, %2, %3;" : "=l"(r) : "l"(a), "l"(b), "l"(c)); return r;
}
__device__ __forceinline__ float2 upk2(unsigned long long a) {
    float2 r; asm("mov.b64 {%0, %1}, %2;" : "=f"(r.x), "=f"(r.y) : "l"(a)); return r;
}
__device__ __forceinline__ unsigned cvt2bf(float hi, float lo) {   // {upper=hi, lower=lo}
    unsigned r; asm("cvt.rn.bf16x2.f32 %0, %1, %2;" : "=r"(r) : "f"(hi), "f"(lo)); return r;
}
__device__ __forceinline__ void hilo(float x, float y, unsigned &hp, unsigned &lp) {
    float xh = __bfloat162float(__float2bfloat16(x));
    float yh = __bfloat162float(__float2bfloat16(y));
    hp = cvt2bf(y, x);
    lp = cvt2bf(y - yh, x - xh);
}
__device__ __forceinline__ void mma16816(float* d, const unsigned* a, const unsigned* b) {
    asm volatile("mma.sync.aligned.m16n8k16.row.col.f32.bf16.bf16.f32 "
        "{%0,%1,%2,%3}, {%4,%5,%6,%7}, {%8,%9}, {%0,%1,%2,%3};"
        : "+f"(d[0]), "+f"(d[1]), "+f"(d[2]), "+f"(d[3])
        : "r"(a[0]), "r"(a[1]), "r"(a[2]), "r"(a[3]), "r"(b[0]), "r"(b[1]));
}
__device__ __forceinline__ void ldsm4(unsigned addr, unsigned &r0, unsigned &r1, unsigned &r2, unsigned &r3) {
    asm volatile("ldmatrix.sync.aligned.m8n8.x4.shared.b16 {%0,%1,%2,%3}, [%4];"
        : "=r"(r0), "=r"(r1), "=r"(r2), "=r"(r3) : "r"(addr));
}
__device__ __forceinline__ unsigned smem_u32(const void* p) {
    unsigned a; asm("{ .reg .u64 t; cvta.to.shared.u64 t, %1; cvt.u32.u64 %0, t; }" : "=r"(a) : "l"(p)); return a;
}

// ---------------- Kernel 1: phi/g projection fused with 2x2 maxpool ----------------
__global__ void __launch_bounds__(256) projpool_kernel(
    const float* __restrict__ x, const float* __restrict__ w_phi, const float* __restrict__ w_g)
{
    __shared__ __align__(16) unsigned long long w2s[C8 * Cc];
    int gy = blockIdx.y;
    const float* w = (gy == 0) ? w_phi : (w_g + (size_t)(gy - 1) * C8 * Cc);
    for (int idx = threadIdx.x; idx < C8 * Cc; idx += 256) { float f = w[idx]; w2s[idx] = pk2(f, f); }
    __syncthreads();

    int t = blockIdx.x * 256 + threadIdx.x;   // 0..8191
    int b = t >> 10, j = t & (HWP - 1);
    int py = j >> 5, px = j & 31;
    const float* xb = x + ((size_t)b << 19) + py * 128 + px * 2;

    unsigned long long a01[C8], a23[C8];
#pragma unroll
    for (int k = 0; k < C8; k++) { a01[k] = 0ULL; a23[k] = 0ULL; }
#pragma unroll 2
    for (int c = 0; c < Cc; c++) {
        const float* p = xb + ((size_t)c << 12);
        unsigned long long x01 = *(const unsigned long long*)p;
        unsigned long long x23 = *(const unsigned long long*)(p + 64);
#pragma unroll
        for (int k = 0; k < C8; k++) {
            unsigned long long w2 = w2s[k * Cc + c];
            a01[k] = fma2(w2, x01, a01[k]);
            a23[k] = fma2(w2, x23, a23[k]);
        }
    }
#pragma unroll
    for (int k = 0; k < C8; k++) {
        float2 v01 = upk2(a01[k]), v23 = upk2(a23[k]);
        float m = fmaxf(fmaxf(v01.x, v01.y), fmaxf(v23.x, v23.y));
        if (gy == 0) phi_g[(((size_t)b * C8 + k) << 10) + j] = m;
        else         gsc_g[(((size_t)b * C2 + (gy - 1) * C8 + k) << 10) + j] = m;
    }
}

// ---------------- Kernel 2: mma.sync flash attention (theta fused via MMA) ----------------
// grid (32, 8), 256 threads. Prologue: theta = x^T @ w_theta^T in 2 K-chunks of 64.
// Main: 8 chunks of 128 j (R11 structure). Epilogue: w_o conv + residual.
// smem (static 41472B, one buffer, phase-reused):
//   prologue: XT_HI[128q][144B] @0, XT_LO @18432, WT_HI[16][144B] @36864, WT_LO @39168
//   loop:     PHI_HI[128j][48B] @0, PHI_LO @6144, G[64c2][272B] @12288
//   epilogue: W_HI[128co][144B] @0, W_LO @18432
#define XT_HI 0
#define XT_LO 18432
#define WT_HI 36864
#define WT_LO 39168
#define PHI_HI 0
#define PHI_LO 6144
#define G_OFF  12288
#define W_HI   0
#define W_LO   18432
#define SMEM_SZ 41472

__global__ void __launch_bounds__(256, 2) attn_kernel(
    const float* __restrict__ x, const float* __restrict__ w_theta,
    const float* __restrict__ w_o, const float* __restrict__ gamma_p,
    float* __restrict__ out)
{
    __shared__ __align__(16) char smem[SMEM_SZ];
    const int tid = threadIdx.x;
    const int w = tid >> 5, lane = tid & 31;
    const int gr = lane >> 2, tig = lane & 3;
    const int b = blockIdx.y;
    const int q0 = blockIdx.x * 128 + w * 16 + gr;
    const int wq = w * 16;
    const unsigned sbase = smem_u32(smem);

    // ldmatrix lane-address decomposition
    const int lrow = lane & 7;
    const int lcolsel = (lane >> 3) & 1;   // 16B column select
    const int lblk = lane >> 4;            // row-block select
    const unsigned phiH = sbase + PHI_HI + (unsigned)((lblk * 8 + lrow) * 48 + lcolsel * 16);
    const unsigned phiL = sbase + PHI_LO + (unsigned)((lblk * 8 + lrow) * 48 + lcolsel * 16);
    const unsigned gB   = sbase + G_OFF  + (unsigned)((lblk * 8 + lrow) * 272 + lcolsel * 16);
    const unsigned wB   = sbase + W_HI   + (unsigned)((lblk * 8 + lrow) * 144 + lcolsel * 16);
    const unsigned xtH  = sbase + XT_HI  + (unsigned)((wq + lblk * 8 + lrow) * 144 + lcolsel * 16);
    const unsigned xtL  = sbase + XT_LO  + (unsigned)((wq + lblk * 8 + lrow) * 144 + lcolsel * 16);
    const unsigned wtH  = sbase + WT_HI  + (unsigned)((lblk * 8 + lrow) * 144 + lcolsel * 16);
    const unsigned wtL  = sbase + WT_LO  + (unsigned)((lblk * 8 + lrow) * 144 + lcolsel * 16);

    // ================= prologue: theta via MMA, 2 K-chunks of 64 =================
    float th_d[2][4];
#pragma unroll
    for (int nt = 0; nt < 2; nt++)
#pragma unroll
        for (int r = 0; r < 4; r++) th_d[nt][r] = 0.0f;

#pragma unroll
    for (int cc = 0; cc < 128; cc += 64) {
        // stage XT chunk: thread (q = tid&127, ch = tid>>7) covers c in [cc+ch*32, +32)
        {
            int q = tid & 127, chh = tid >> 7;
            const float* xsrc = x + ((size_t)b << 19) + blockIdx.x * 128 + q;
            char* hb = smem + XT_HI + q * 144 + chh * 64;
            char* lb = smem + XT_LO + q * 144 + chh * 64;
#pragma unroll
            for (int u = 0; u < 16; u++) {
                int c = cc + chh * 32 + u * 2;
                float v0 = xsrc[(size_t)c << 12], v1 = xsrc[(size_t)(c + 1) << 12];
                unsigned hp, lp; hilo(v0, v1, hp, lp);
                *(unsigned*)(hb + u * 4) = hp;
                *(unsigned*)(lb + u * 4) = lp;
            }
        }
        // stage WT chunk: 16 n x 32 c-pairs
        for (int idx = tid; idx < 512; idx += 256) {
            int n = idx >> 5, cp = idx & 31;
            int c = cc + cp * 2;
            float v0 = w_theta[n * 128 + c], v1 = w_theta[n * 128 + c + 1];
            unsigned hp, lp; hilo(v0, v1, hp, lp);
            *(unsigned*)(smem + WT_HI + n * 144 + cp * 4) = hp;
            *(unsigned*)(smem + WT_LO + n * 144 + cp * 4) = lp;
        }
        __syncthreads();

#pragma unroll
        for (int kc = 0; kc < 4; kc++) {
            unsigned r0, r1, r2, r3;
            ldsm4(xtH + (unsigned)kc * 32u, r0, r1, r2, r3);
            unsigned xh[4] = { r0, r2, r1, r3 };    // A-frag permute
            ldsm4(xtL + (unsigned)kc * 32u, r0, r1, r2, r3);
            unsigned xl[4] = { r0, r2, r1, r3 };
            unsigned w0, w1, w2, w3, v0, v1, v2, v3;
            ldsm4(wtH + (unsigned)kc * 32u, w0, w1, w2, w3);
            ldsm4(wtL + (unsigned)kc * 32u, v0, v1, v2, v3);
            unsigned bh0[2] = { w0, w1 }, bh1[2] = { w2, w3 };
            unsigned bl0[2] = { v0, v1 }, bl1[2] = { v2, v3 };
            mma16816(th_d[0], xh, bh0);
            mma16816(th_d[0], xh, bl0);
            mma16816(th_d[0], xl, bh0);
            mma16816(th_d[1], xh, bh1);
            mma16816(th_d[1], xh, bl1);
            mma16816(th_d[1], xl, bh1);
        }
        __syncthreads();
    }

    // theta D-frag -> S-MMA A-frag (hi/lo)
    unsigned ahi[4], alo[4];
    hilo(th_d[0][0], th_d[0][1], ahi[0], alo[0]);
    hilo(th_d[0][2], th_d[0][3], ahi[1], alo[1]);
    hilo(th_d[1][0], th_d[1][1], ahi[2], alo[2]);
    hilo(th_d[1][2], th_d[1][3], ahi[3], alo[3]);

    // ================= main loop (R11 structure) =================
    float oacc[8][4];
#pragma unroll
    for (int nt = 0; nt < 8; nt++)
#pragma unroll
        for (int r = 0; r < 4; r++) oacc[nt][r] = 0.0f;
    float es0 = 0.0f, es1 = 0.0f;

    for (int ch = 0; ch < 8; ch++) {
        const int j0 = ch << 7;
        // ---- stage phi chunk -> [j][k] bf16 hi/lo, row stride 48B ----
        {
            int jj = tid & 127, ks = (tid >> 7) << 3;
            const float* src = phi_g + (((size_t)(b * 16 + ks)) << 10) + j0 + jj;
            char* hb = smem + PHI_HI + jj * 48 + ks * 2;
            char* lb = smem + PHI_LO + jj * 48 + ks * 2;
#pragma unroll
            for (int u = 0; u < 8; u++) {
                float v = src[(size_t)u << 10];
                float vh = __bfloat162float(__float2bfloat16(v));
                *(__nv_bfloat16*)(hb + 2 * u) = __float2bfloat16(v);
                *(__nv_bfloat16*)(lb + 2 * u) = __float2bfloat16(v - vh);
            }
        }
        // ---- stage g chunk -> [c2][j] bf16 (hi only), row stride 272B ----
        {
            int c2 = tid >> 2, jq = (tid & 3) << 5;
            const float4* src = (const float4*)(gsc_g + (((size_t)(b * 64 + c2)) << 10) + j0 + jq);
            char* dst = smem + G_OFF + c2 * 272 + jq * 2;
#pragma unroll
            for (int u = 0; u < 8; u++) {
                float4 v = src[u];
                unsigned p0 = cvt2bf(v.y, v.x), p1 = cvt2bf(v.w, v.z);
                *(unsigned long long*)(dst + 8 * u) = ((unsigned long long)p1 << 32) | p0;
            }
        }
        __syncthreads();

        // ---- S phase: 8 tile-pairs via ldmatrix, exp, pack P ----
        unsigned pp[16][2];
#pragma unroll
        for (int tp = 0; tp < 8; tp++) {
            unsigned h0, h1, h2, h3, l0, l1, l2, l3;
            ldsm4(phiH + tp * 768u, h0, h1, h2, h3);
            ldsm4(phiL + tp * 768u, l0, l1, l2, l3);
            {
                unsigned bh[2] = { h0, h1 }, bl[2] = { l0, l1 };
                float d[4] = {0.f, 0.f, 0.f, 0.f};
                mma16816(d, ahi, bh);
                mma16816(d, ahi, bl);
                mma16816(d, alo, bh);
                float e0 = __expf(d[0]), e1 = __expf(d[1]), e2 = __expf(d[2]), e3 = __expf(d[3]);
                es0 += e0 + e1; es1 += e2 + e3;
                pp[2*tp][0] = cvt2bf(e1, e0);
                pp[2*tp][1] = cvt2bf(e3, e2);
            }
            {
                unsigned bh[2] = { h2, h3 }, bl[2] = { l2, l3 };
                float d[4] = {0.f, 0.f, 0.f, 0.f};
                mma16816(d, ahi, bh);
                mma16816(d, ahi, bl);
                mma16816(d, alo, bh);
                float e0 = __expf(d[0]), e1 = __expf(d[1]), e2 = __expf(d[2]), e3 = __expf(d[3]);
                es0 += e0 + e1; es1 += e2 + e3;
                pp[2*tp+1][0] = cvt2bf(e1, e0);
                pp[2*tp+1][1] = cvt2bf(e3, e2);
            }
        }
        // ---- O phase: O += P @ g^T ----
#pragma unroll
        for (int kk = 0; kk < 8; kk++) {
            unsigned a[4] = { pp[2*kk][0], pp[2*kk][1], pp[2*kk+1][0], pp[2*kk+1][1] };
#pragma unroll
            for (int u = 0; u < 4; u++) {
                unsigned g0, g1, g2, g3;
                ldsm4(gB + (unsigned)(u * 16 * 272 + kk * 32), g0, g1, g2, g3);
                unsigned b0[2] = { g0, g1 }, b1[2] = { g2, g3 };
                mma16816(oacc[2*u],     a, b0);
                mma16816(oacc[2*u + 1], a, b1);
            }
        }
        __syncthreads();
    }

    // ---- softmax normalization ----
    es0 += __shfl_xor_sync(0xFFFFFFFFu, es0, 1);
    es0 += __shfl_xor_sync(0xFFFFFFFFu, es0, 2);
    es1 += __shfl_xor_sync(0xFFFFFFFFu, es1, 1);
    es1 += __shfl_xor_sync(0xFFFFFFFFu, es1, 2);
    float i0 = 1.0f / es0, i1 = 1.0f / es1;
#pragma unroll
    for (int nt = 0; nt < 8; nt++) {
        oacc[nt][0] *= i0; oacc[nt][1] *= i0;
        oacc[nt][2] *= i1; oacc[nt][3] *= i1;
    }

    // ---- stage w_o -> [co][c2] bf16 hi/lo, row stride 144B ----
    {
        int co = tid >> 1, c2h = (tid & 1) << 5;
        const float4* src = (const float4*)(w_o + co * 64 + c2h);
        char* dh = smem + W_HI + co * 144 + c2h * 2;
        char* dl = smem + W_LO + co * 144 + c2h * 2;
#pragma unroll
        for (int u = 0; u < 8; u++) {
            float4 v = src[u];
            float hx = __bfloat162float(__float2bfloat16(v.x));
            float hy = __bfloat162float(__float2bfloat16(v.y));
            float hz = __bfloat162float(__float2bfloat16(v.z));
            float hw = __bfloat162float(__float2bfloat16(v.w));
            unsigned h0 = cvt2bf(v.y, v.x), h1 = cvt2bf(v.w, v.z);
            unsigned l0 = cvt2bf(v.y - hy, v.x - hx), l1 = cvt2bf(v.w - hw, v.z - hz);
            *(unsigned long long*)(dh + 8 * u) = ((unsigned long long)h1 << 32) | h0;
            *(unsigned long long*)(dl + 8 * u) = ((unsigned long long)l1 << 32) | l0;
        }
    }
    __syncthreads();

    // ---- out = gamma * (o @ w_o^T) + x ----
    const float gamma = *gamma_p;
    const float* xb = x   + ((size_t)b << 19);
    float*       ob = out + ((size_t)b << 19);

    unsigned oa[4][4];
#pragma unroll
    for (int kk = 0; kk < 4; kk++) {
        oa[kk][0] = cvt2bf(oacc[2*kk][1],   oacc[2*kk][0]);
        oa[kk][1] = cvt2bf(oacc[2*kk][3],   oacc[2*kk][2]);
        oa[kk][2] = cvt2bf(oacc[2*kk+1][1], oacc[2*kk+1][0]);
        oa[kk][3] = cvt2bf(oacc[2*kk+1][3], oacc[2*kk+1][2]);
    }

#pragma unroll
    for (int h = 0; h < 2; h++) {
        float dd[8][4];
#pragma unroll
        for (int nt = 0; nt < 8; nt++)
#pragma unroll
            for (int r = 0; r < 4; r++) dd[nt][r] = 0.0f;
#pragma unroll
        for (int kk = 0; kk < 4; kk++) {
#pragma unroll
            for (int u = 0; u < 4; u++) {
                unsigned wh0, wh1, wh2, wh3, wl0, wl1, wl2, wl3;
                unsigned off = (unsigned)((h * 64 + u * 16) * 144 + kk * 32);
                ldsm4(wB + off,                   wh0, wh1, wh2, wh3);
                ldsm4(wB + off + (unsigned)W_LO, wl0, wl1, wl2, wl3);
                unsigned b0[2] = { wh0, wh1 }, b1[2] = { wl0, wl1 };
                unsigned b2[2] = { wh2, wh3 }, b3[2] = { wl2, wl3 };
                mma16816(dd[2*u],     oa[kk], b0);
                mma16816(dd[2*u],     oa[kk], b1);
                mma16816(dd[2*u + 1], oa[kk], b2);
                mma16816(dd[2*u + 1], oa[kk], b3);
            }
        }
#pragma unroll
        for (int nt = 0; nt < 8; nt++) {
            int co0 = (((h << 3) + nt) * 8 + tig * 2);
            size_t i00 = ((size_t)co0 << 12) + q0;
            size_t i01 = ((size_t)(co0 + 1) << 12) + q0;
            ob[i00]     = fmaf(gamma, dd[nt][0], xb[i00]);
            ob[i01]     = fmaf(gamma, dd[nt][1], xb[i01]);
            ob[i00 + 8] = fmaf(gamma, dd[nt][2], xb[i00 + 8]);
            ob[i01 + 8] = fmaf(gamma, dd[nt][3], xb[i01 + 8]);
        }
    }
}

extern "C" void kernel_launch(void* const* d_in, const int* in_sizes, int n_in,
                              void* d_out, int out_size)
{
    const float* x       = (const float*)d_in[0];
    const float* w_theta = (const float*)d_in[1];
    const float* w_phi   = (const float*)d_in[2];
    const float* w_g     = (const float*)d_in[3];
    const float* w_o     = (const float*)d_in[4];
    const float* gamma_p = (const float*)d_in[5];
    float* out = (float*)d_out;

    projpool_kernel<<<dim3(32, 5), 256>>>(x, w_phi, w_g);
    attn_kernel<<<dim3(32, 8), 256>>>(x, w_theta, w_o, gamma_p, out);
}